// round 4
// baseline (speedup 1.0000x reference)
#include <cuda_runtime.h>
#include <cstdint>

#define B_    4
#define T_    1024
#define DIM_  512
#define POOL_ 64
#define K_    50
#define TK_   2      // tokens per k1 block

// Scratch (device globals: allocation-free per harness rules)
__device__ int   g_idx[T_ * K_];                          // top-50 indices per t
__device__ __align__(16) float g_z[B_ * POOL_ * DIM_];    // z[b][j][d]

// packed fp32x2 FMA (Blackwell FFMA2 — only reachable via PTX)
#define FMA2(d, a, b) \
    asm("fma.rn.f32x2 %0, %1, %2, %3;" : "=l"(d) : "l"(a), "l"(b), "l"(d))
#define PACK_DUP(dst, w) \
    asm("mov.b64 %0, {%1, %1};" : "=l"(dst) : "f"(w))
#define UNPACK2(lo, hi, v) \
    asm("mov.b64 {%0, %1}, %2;" : "=f"(lo), "=f"(hi) : "l"(v))
#define LDS_V2U64(a0, a1, addr) \
    asm("ld.shared.v2.b64 {%0, %1}, [%2];" : "=l"(a0), "=l"(a1) : "r"(addr))

// ---------------------------------------------------------------------------
// Kernel 1 (fused): 2 tokens/block, grid=512, block=256.
//  stage A: Linear(512->64)+ReLU+LN for 4 batches x 2 tokens (FFMA2 packed
//           over the token pair), batch-sum, stable top-50 per token.
//  stage B: blocks owning tokens t<64 also compute
//           z[b,t,:] = LN(relu(y[b,t,:] @ w2 + b2))  (warp-per-row).
// ---------------------------------------------------------------------------
__global__ __launch_bounds__(256) void k1_fused(
        const float* __restrict__ x,
        const float* __restrict__ w1,
        const float* __restrict__ b1,
        const float* __restrict__ g1,
        const float* __restrict__ bt1,
        const float* __restrict__ w2,
        const float* __restrict__ b2,
        const float* __restrict__ g2,
        const float* __restrict__ bt2) {
    // smem
    __shared__ __align__(16) float xs[B_ * DIM_ * 2];     // (tk0,tk1) pairs, 16KB
    __shared__ float part[B_ * TK_ * 4 * POOL_];          // partial dots, 8KB
    __shared__ float yrow[B_ * TK_ * POOL_];              // y rows, 2KB
    __shared__ float sv[TK_ * POOL_];                     // batch-summed y
    __shared__ float wsum[4][B_], wsq[4][B_];             // 4 tail warps

    const int t0  = blockIdx.x * TK_;
    const int tid = threadIdx.x;
    const int p   = tid & 63;    // pool index
    const int c   = tid >> 6;    // DIM chunk 0..3

    uint32_t sx;
    asm("{ .reg .u64 t; cvta.to.shared.u64 t, %1; cvt.u32.u64 %0, t; }"
        : "=r"(sx) : "l"(xs));

    // ---- load x rows, interleaving the token pair ----
    // i indexes (b, d4-group): 4*128 = 512 groups, 2 per thread
    #pragma unroll
    for (int i = tid; i < B_ * (DIM_ / 4); i += 256) {
        int b = i >> 7, j = i & 127;                       // j = d/4
        const float* xb = x + ((size_t)b * T_ + t0) * DIM_;
        float4 v0 = reinterpret_cast<const float4*>(xb)[j];
        float4 v1 = reinterpret_cast<const float4*>(xb + DIM_)[j];
        float* dst = xs + b * (DIM_ * 2) + j * 8;          // 8 floats: 4 pairs
        dst[0] = v0.x; dst[1] = v1.x;
        dst[2] = v0.y; dst[3] = v1.y;
        dst[4] = v0.z; dst[5] = v1.z;
        dst[6] = v0.w; dst[7] = v1.w;
    }
    __syncthreads();

    // ---- main GEMM: 128 dims/thread, 4 batches, packed token pair ----
    unsigned long long acc[B_] = {};
    const float* wbase = w1 + (c * 128) * POOL_ + p;
    const uint32_t dbase = sx + (uint32_t)(c * 128) * 8u;  // byte offset: dim*8

    #pragma unroll 8
    for (int d4 = 0; d4 < 32; d4++) {
        const float* wp = wbase + d4 * 4 * POOL_;
        unsigned long long wwa, wwb, wwc, wwd;
        PACK_DUP(wwa, wp[0]);
        PACK_DUP(wwb, wp[POOL_]);
        PACK_DUP(wwc, wp[2 * POOL_]);
        PACK_DUP(wwd, wp[3 * POOL_]);
        #pragma unroll
        for (int b = 0; b < B_; b++) {
            uint32_t a0 = dbase + (uint32_t)(b * 4096 + d4 * 32);
            unsigned long long v0, v1, v2, v3;
            LDS_V2U64(v0, v1, a0);
            LDS_V2U64(v2, v3, a0 + 16);
            FMA2(acc[b], v0, wwa);
            FMA2(acc[b], v1, wwb);
            FMA2(acc[b], v2, wwc);
            FMA2(acc[b], v3, wwd);
        }
    }
    #pragma unroll
    for (int b = 0; b < B_; b++) {
        float lo, hi;
        UNPACK2(lo, hi, acc[b]);
        part[((b * TK_ + 0) * 4 + c) * POOL_ + p] = lo;
        part[((b * TK_ + 1) * 4 + c) * POOL_ + p] = hi;
    }
    __syncthreads();

    // ---- tail: LN + topk on first 128 threads (tk = tid>>6, pp = tid&63) ----
    if (tid < TK_ * POOL_) {
        const int tk = tid >> 6;
        const int pp = tid & 63;
        const int t  = t0 + tk;
        const float bias = b1[pp];

        float vv[B_];
        #pragma unroll
        for (int b = 0; b < B_; b++) {
            const float* pb = part + ((b * TK_ + tk) * 4) * POOL_ + pp;
            vv[b] = fmaxf(pb[0] + pb[POOL_] + pb[2 * POOL_] + pb[3 * POOL_]
                          + bias, 0.f);
        }

        float s[B_], q[B_];
        #pragma unroll
        for (int b = 0; b < B_; b++) { s[b] = vv[b]; q[b] = vv[b] * vv[b]; }
        #pragma unroll
        for (int off = 16; off > 0; off >>= 1) {
            #pragma unroll
            for (int b = 0; b < B_; b++) {
                s[b] += __shfl_xor_sync(0xffffffffu, s[b], off);
                q[b] += __shfl_xor_sync(0xffffffffu, q[b], off);
            }
        }
        const int w = tid >> 5;   // warps 0..3 (2 per token)
        if ((tid & 31) == 0) {
            #pragma unroll
            for (int b = 0; b < B_; b++) { wsum[w][b] = s[b]; wsq[w][b] = q[b]; }
        }
    }
    __syncthreads();
    if (tid < TK_ * POOL_) {
        const int tk = tid >> 6;
        const int pp = tid & 63;
        const int t  = t0 + tk;
        const float gp = g1[pp], bp = bt1[pp];

        float vv[B_];
        #pragma unroll
        for (int b = 0; b < B_; b++) {
            const float* pb = part + ((b * TK_ + tk) * 4) * POOL_ + pp;
            vv[b] = fmaxf(pb[0] + pb[POOL_] + pb[2 * POOL_] + pb[3 * POOL_]
                          + b1[pp], 0.f);
        }

        float ysum = 0.f;
        #pragma unroll
        for (int b = 0; b < B_; b++) {
            float S = wsum[tk * 2][b] + wsq[0][0] * 0.f + wsum[tk * 2 + 1][b];
            float Q = wsq[tk * 2][b] + wsq[tk * 2 + 1][b];
            float m   = S * (1.f / POOL_);
            float var = Q * (1.f / POOL_) - m * m;
            float r   = rsqrtf(var + 1e-5f);
            float yv = (vv[b] - m) * r * gp + bp;
            yrow[(b * TK_ + tk) * POOL_ + pp] = yv;
            ysum += yv;
        }
        sv[tk * POOL_ + pp] = ysum;
        __syncwarp();
        asm volatile("bar.sync 1, 128;" ::: "memory");

        const float mine = ysum;
        int rank = 0;
        #pragma unroll
        for (int j = 0; j < POOL_; j++) {
            float o = sv[tk * POOL_ + j];
            rank += (o > mine) || ((o == mine) && (j < pp));
        }
        if (rank < K_) g_idx[t * K_ + rank] = pp;
    }

    // ---- stage B: z rows for t<64 (blocks 0..31), warp-per-(b,tk) row ----
    if (t0 < POOL_) {
        __syncthreads();          // yrow complete
        const int warp = tid >> 5;       // 0..7 -> (b, tk)
        const int lane = tid & 31;
        const int b  = warp >> 1;
        const int tk = warp & 1;
        const int t  = t0 + tk;
        const float* yr = yrow + (b * TK_ + tk) * POOL_;

        // dims: chunk i in [0,4): d = i*128 + lane*4 .. +3
        float4 accz[4];
        #pragma unroll
        for (int i = 0; i < 4; i++)
            accz[i] = reinterpret_cast<const float4*>(b2)[i * 32 + lane];

        #pragma unroll 4
        for (int pp = 0; pp < POOL_; pp++) {
            float yv = yr[pp];
            const float4* wr = reinterpret_cast<const float4*>(w2 + pp * DIM_);
            #pragma unroll
            for (int i = 0; i < 4; i++) {
                float4 wv = wr[i * 32 + lane];
                accz[i].x += yv * wv.x;
                accz[i].y += yv * wv.y;
                accz[i].z += yv * wv.z;
                accz[i].w += yv * wv.w;
            }
        }
        float s = 0.f, q = 0.f;
        #pragma unroll
        for (int i = 0; i < 4; i++) {
            accz[i].x = fmaxf(accz[i].x, 0.f);
            accz[i].y = fmaxf(accz[i].y, 0.f);
            accz[i].z = fmaxf(accz[i].z, 0.f);
            accz[i].w = fmaxf(accz[i].w, 0.f);
            s += accz[i].x + accz[i].y + accz[i].z + accz[i].w;
            q += accz[i].x * accz[i].x + accz[i].y * accz[i].y
               + accz[i].z * accz[i].z + accz[i].w * accz[i].w;
        }
        #pragma unroll
        for (int off = 16; off > 0; off >>= 1) {
            s += __shfl_xor_sync(0xffffffffu, s, off);
            q += __shfl_xor_sync(0xffffffffu, q, off);
        }
        float m   = s * (1.f / DIM_);
        float var = q * (1.f / DIM_) - m * m;
        float r   = rsqrtf(var + 1e-5f);

        float4* zr = reinterpret_cast<float4*>(g_z + ((size_t)b * POOL_ + t) * DIM_);
        #pragma unroll
        for (int i = 0; i < 4; i++) {
            float4 gv = reinterpret_cast<const float4*>(g2)[i * 32 + lane];
            float4 bv = reinterpret_cast<const float4*>(bt2)[i * 32 + lane];
            float4 o;
            o.x = (accz[i].x - m) * r * gv.x + bv.x;
            o.y = (accz[i].y - m) * r * gv.y + bv.y;
            o.z = (accz[i].z - m) * r * gv.z + bv.z;
            o.w = (accz[i].w - m) * r * gv.w + bv.w;
            zr[i * 32 + lane] = o;
        }
    }
}

// ---------------------------------------------------------------------------
// Kernel 3: out[b,t,k,:] = z[b, idx[t,k], :]  — the 419 MB write stream.
// ---------------------------------------------------------------------------
__global__ void k3_gather(float* __restrict__ out) {
    const int warp = threadIdx.x >> 5;
    const int lane = threadIdx.x & 31;
    const unsigned base = blockIdx.x * 64u;

    #pragma unroll
    for (int i = 0; i < 4; i++) {
        unsigned r   = base + warp + i * 16;
        unsigned b   = r / (unsigned)(T_ * K_);
        unsigned rem = r - b * (unsigned)(T_ * K_);
        unsigned t   = rem / K_;
        unsigned k   = rem - t * K_;
        int j = g_idx[t * K_ + k];

        const float4* src = reinterpret_cast<const float4*>(g_z)
                            + (size_t)(b * POOL_ + j) * (DIM_ / 4);
        float4* dst = reinterpret_cast<float4*>(out)
                      + (size_t)r * (DIM_ / 4);
        #pragma unroll
        for (int cc = 0; cc < 4; cc++) {
            float4 v = __ldg(src + lane + 32 * cc);
            __stcs(dst + lane + 32 * cc, v);
        }
    }
}

// ---------------------------------------------------------------------------
extern "C" void kernel_launch(void* const* d_in, const int* in_sizes, int n_in,
                              void* d_out, int out_size) {
    const float* x   = (const float*)d_in[0];
    const float* w1  = (const float*)d_in[1];
    const float* b1  = (const float*)d_in[2];
    const float* g1  = (const float*)d_in[3];
    const float* bt1 = (const float*)d_in[4];
    const float* w2  = (const float*)d_in[5];
    const float* b2  = (const float*)d_in[6];
    const float* g2  = (const float*)d_in[7];
    const float* bt2 = (const float*)d_in[8];
    float* out = (float*)d_out;

    k1_fused<<<T_ / TK_, 256>>>(x, w1, b1, g1, bt1, w2, b2, g2, bt2);
    k3_gather<<<(B_ * T_ * K_) / 64, 512>>>(out);
}

// round 5
// speedup vs baseline: 1.1606x; 1.1606x over previous
#include <cuda_runtime.h>
#include <cstdint>

#define B_    4
#define T_    1024
#define DIM_  512
#define POOL_ 64
#define K_    50
#define TK_   2      // tokens per k1 block (packed in f32x2)

// Scratch (device globals: allocation-free per harness rules)
__device__ __align__(16) float g_y[B_ * POOL_ * POOL_];   // y[b][t<64][p]
__device__ int   g_idx[T_ * K_];                          // top-50 indices per t
__device__ __align__(16) float g_z[B_ * POOL_ * DIM_];    // z[b][j][d]

// packed fp32x2 ops (Blackwell FFMA2 — only reachable via PTX)
#define FMA2(d, a, b) \
    asm("fma.rn.f32x2 %0, %1, %2, %3;" : "=l"(d) : "l"(a), "l"(b), "l"(d))
#define ADD2(d, a, b) \
    asm("add.rn.f32x2 %0, %1, %2;" : "=l"(d) : "l"(a), "l"(b))
#define PACK_DUP(dst, w) \
    asm("mov.b64 %0, {%1, %1};" : "=l"(dst) : "f"(w))
#define PACK2(dst, lo, hi) \
    asm("mov.b64 %0, {%1, %2};" : "=l"(dst) : "f"(lo), "f"(hi))
#define UNPACK2(lo, hi, v) \
    asm("mov.b64 {%0, %1}, %2;" : "=f"(lo), "=f"(hi) : "l"(v))
#define LDS_V2U64(a0, a1, addr) \
    asm("ld.shared.v2.b64 {%0, %1}, [%2];" : "=l"(a0), "=l"(a1) : "r"(addr))

// ---------------------------------------------------------------------------
// Kernel 1: 2 tokens/block, grid=512, block=256.
// Register-blocked: thread (dc = tid>>4, pg = tid&15) computes pool outputs
// pg*4..pg*4+3 for all 4 batches over dims [dc*32, dc*32+32), token pair
// packed in f32x2 accumulators. Butterfly-shuffle + smem reduce over dc,
// then LN + stable top-50 tail on first 128 threads.
// ---------------------------------------------------------------------------
__global__ __launch_bounds__(256) void k1_reduce_topk(
        const float* __restrict__ x,
        const float* __restrict__ w1,
        const float* __restrict__ b1,
        const float* __restrict__ g1,
        const float* __restrict__ bt1) {
    // pool: phase 1 = x pairs, u64[b][d] (4*512*8B = 16KB)
    //       phase 2 = partials, float[warp][row8][64]  (8*8*64*4B = 16KB)
    __shared__ __align__(16) float pool[4096];
    __shared__ float sv[TK_ * POOL_];
    __shared__ float wsum[4][B_], wsq[4][B_];

    const int t0  = blockIdx.x * TK_;
    const int tid = threadIdx.x;
    const int pg  = tid & 15;    // pool group: outputs pg*4 .. pg*4+3
    const int dc  = tid >> 4;    // dim chunk: dims dc*32 .. dc*32+31

    uint32_t sx;
    asm("{ .reg .u64 t; cvta.to.shared.u64 t, %1; cvt.u32.u64 %0, t; }"
        : "=r"(sx) : "l"(pool));

    // ---- phase 1 load: interleave token pair into u64 lanes ----
    float2* poolf2 = reinterpret_cast<float2*>(pool);
    #pragma unroll
    for (int i = tid; i < B_ * (DIM_ / 4); i += 256) {   // 512 float4 groups
        int b = i >> 7, j = i & 127;                      // j = d/4
        const float* xb = x + ((size_t)b * T_ + t0) * DIM_;
        float4 v0 = reinterpret_cast<const float4*>(xb)[j];
        float4 v1 = reinterpret_cast<const float4*>(xb + DIM_)[j];
        float2* dst = poolf2 + b * DIM_ + j * 4;
        dst[0] = make_float2(v0.x, v1.x);
        dst[1] = make_float2(v0.y, v1.y);
        dst[2] = make_float2(v0.z, v1.z);
        dst[3] = make_float2(v0.w, v1.w);
    }
    __syncthreads();

    // ---- main loop: 32 dims, 4 batches, 4 pools, token pair packed ----
    unsigned long long acc[B_][4] = {};
    const float4* w1v = reinterpret_cast<const float4*>(w1);  // [d*16 + pg]

    #pragma unroll
    for (int d2 = 0; d2 < 16; d2++) {
        const int d = dc * 32 + d2 * 2;
        float4 wv0 = __ldg(w1v + (size_t)d * 16 + pg);        // dim d,   pools pg*4..+3
        float4 wv1 = __ldg(w1v + (size_t)(d + 1) * 16 + pg);  // dim d+1
        unsigned long long w00, w01, w02, w03, w10, w11, w12, w13;
        PACK_DUP(w00, wv0.x); PACK_DUP(w01, wv0.y);
        PACK_DUP(w02, wv0.z); PACK_DUP(w03, wv0.w);
        PACK_DUP(w10, wv1.x); PACK_DUP(w11, wv1.y);
        PACK_DUP(w12, wv1.z); PACK_DUP(w13, wv1.w);

        #pragma unroll
        for (int b = 0; b < B_; b++) {
            unsigned long long xv0, xv1;   // x pairs for dims d, d+1
            LDS_V2U64(xv0, xv1, sx + (uint32_t)((b * DIM_ + d) * 8));
            FMA2(acc[b][0], xv0, w00);  FMA2(acc[b][0], xv1, w10);
            FMA2(acc[b][1], xv0, w01);  FMA2(acc[b][1], xv1, w11);
            FMA2(acc[b][2], xv0, w02);  FMA2(acc[b][2], xv1, w12);
            FMA2(acc[b][3], xv0, w03);  FMA2(acc[b][3], xv1, w13);
        }
    }

    // ---- reduce over dc: butterfly within warp (dc pairs), then smem ----
    #pragma unroll
    for (int b = 0; b < B_; b++) {
        #pragma unroll
        for (int pl = 0; pl < 4; pl++) {
            unsigned long long o =
                __shfl_xor_sync(0xffffffffu, acc[b][pl], 16);
            ADD2(acc[b][pl], acc[b][pl], o);
        }
    }
    __syncthreads();   // all xs reads done; pool becomes partial buffer

    if ((tid & 16) == 0) {          // one lane per (warp, pg)
        const int w = tid >> 5;     // 0..7
        #pragma unroll
        for (int b = 0; b < B_; b++) {
            #pragma unroll
            for (int pl = 0; pl < 4; pl++) {
                float lo, hi;
                UNPACK2(lo, hi, acc[b][pl]);
                pool[w * 512 + (b * TK_ + 0) * 64 + pg * 4 + pl] = lo;
                pool[w * 512 + (b * TK_ + 1) * 64 + pg * 4 + pl] = hi;
            }
        }
    }
    __syncthreads();

    // ---- tail on first 128 threads: tk = tid>>6, pp = tid&63 ----
    float vv[B_];
    if (tid < TK_ * POOL_) {
        const int tk = tid >> 6;
        const int pp = tid & 63;
        const float bias = b1[pp];

        #pragma unroll
        for (int b = 0; b < B_; b++) {
            float a = bias;
            #pragma unroll
            for (int w = 0; w < 8; w++)
                a += pool[w * 512 + (b * TK_ + tk) * 64 + pp];
            vv[b] = fmaxf(a, 0.f);
        }

        float s[B_], q[B_];
        #pragma unroll
        for (int b = 0; b < B_; b++) { s[b] = vv[b]; q[b] = vv[b] * vv[b]; }
        #pragma unroll
        for (int off = 16; off > 0; off >>= 1) {
            #pragma unroll
            for (int b = 0; b < B_; b++) {
                s[b] += __shfl_xor_sync(0xffffffffu, s[b], off);
                q[b] += __shfl_xor_sync(0xffffffffu, q[b], off);
            }
        }
        const int w = tid >> 5;   // warps 0..3 (2 per token)
        if ((tid & 31) == 0) {
            #pragma unroll
            for (int b = 0; b < B_; b++) { wsum[w][b] = s[b]; wsq[w][b] = q[b]; }
        }
    }
    __syncthreads();

    if (tid < TK_ * POOL_) {
        const int tk = tid >> 6;
        const int pp = tid & 63;
        const int t  = t0 + tk;
        const float gp = g1[pp], bp = bt1[pp];

        float ysum = 0.f;
        float yv[B_];
        #pragma unroll
        for (int b = 0; b < B_; b++) {
            float S = wsum[tk * 2][b] + wsum[tk * 2 + 1][b];
            float Q = wsq[tk * 2][b]  + wsq[tk * 2 + 1][b];
            float m   = S * (1.f / POOL_);
            float var = Q * (1.f / POOL_) - m * m;
            float r   = rsqrtf(var + 1e-5f);
            yv[b] = (vv[b] - m) * r * gp + bp;
            ysum += yv[b];
        }

        if (t < POOL_) {
            #pragma unroll
            for (int b = 0; b < B_; b++)
                g_y[(b * POOL_ + t) * POOL_ + pp] = yv[b];
        }

        sv[tk * POOL_ + pp] = ysum;
        __syncwarp();
        asm volatile("bar.sync 1, 128;" ::: "memory");

        const float mine = ysum;
        int rank = 0;
        #pragma unroll
        for (int j = 0; j < POOL_; j++) {
            float o = sv[tk * POOL_ + j];
            rank += (o > mine) || ((o == mine) && (j < pp));
        }
        if (rank < K_) g_idx[t * K_ + rank] = pp;
    }
}

// ---------------------------------------------------------------------------
// Kernel 2: z[b,j,:] = LN(relu(y[b,j,:] @ w2 + b2))   (256 distinct rows)
// grid = B_*POOL_, block = 512
// ---------------------------------------------------------------------------
__global__ void k2_expand(const float* __restrict__ w2,
                          const float* __restrict__ b2,
                          const float* __restrict__ g2,
                          const float* __restrict__ bt2) {
    const int bj = blockIdx.x;
    const int d  = threadIdx.x;

    __shared__ float yr[POOL_];
    if (d < POOL_) yr[d] = g_y[bj * POOL_ + d];
    __syncthreads();

    float acc = b2[d];
    #pragma unroll
    for (int p = 0; p < POOL_; p++)
        acc += yr[p] * w2[p * DIM_ + d];

    float v = fmaxf(acc, 0.f);

    float s = v, q = v * v;
    #pragma unroll
    for (int off = 16; off > 0; off >>= 1) {
        s += __shfl_xor_sync(0xffffffffu, s, off);
        q += __shfl_xor_sync(0xffffffffu, q, off);
    }
    __shared__ float ps[16], pq[16];
    const int w = d >> 5;
    if ((d & 31) == 0) { ps[w] = s; pq[w] = q; }
    __syncthreads();
    float S = 0.f, Q = 0.f;
    #pragma unroll
    for (int i = 0; i < 16; i++) { S += ps[i]; Q += pq[i]; }

    float m   = S * (1.f / DIM_);
    float var = Q * (1.f / DIM_) - m * m;
    g_z[bj * DIM_ + d] = (v - m) * rsqrtf(var + 1e-5f) * g2[d] + bt2[d];
}

// ---------------------------------------------------------------------------
// Kernel 3: out[b,t,k,:] = z[b, idx[t,k], :]  — the 419 MB write stream.
// At the HBM-write roofline (76% DRAM). Unchanged.
// ---------------------------------------------------------------------------
__global__ void k3_gather(float* __restrict__ out) {
    const int warp = threadIdx.x >> 5;
    const int lane = threadIdx.x & 31;
    const unsigned base = blockIdx.x * 64u;

    #pragma unroll
    for (int i = 0; i < 4; i++) {
        unsigned r   = base + warp + i * 16;
        unsigned b   = r / (unsigned)(T_ * K_);
        unsigned rem = r - b * (unsigned)(T_ * K_);
        unsigned t   = rem / K_;
        unsigned k   = rem - t * K_;
        int j = g_idx[t * K_ + k];

        const float4* src = reinterpret_cast<const float4*>(g_z)
                            + (size_t)(b * POOL_ + j) * (DIM_ / 4);
        float4* dst = reinterpret_cast<float4*>(out)
                      + (size_t)r * (DIM_ / 4);
        #pragma unroll
        for (int cc = 0; cc < 4; cc++) {
            float4 v = __ldg(src + lane + 32 * cc);
            __stcs(dst + lane + 32 * cc, v);
        }
    }
}

// ---------------------------------------------------------------------------
extern "C" void kernel_launch(void* const* d_in, const int* in_sizes, int n_in,
                              void* d_out, int out_size) {
    const float* x   = (const float*)d_in[0];
    const float* w1  = (const float*)d_in[1];
    const float* b1  = (const float*)d_in[2];
    const float* g1  = (const float*)d_in[3];
    const float* bt1 = (const float*)d_in[4];
    const float* w2  = (const float*)d_in[5];
    const float* b2  = (const float*)d_in[6];
    const float* g2  = (const float*)d_in[7];
    const float* bt2 = (const float*)d_in[8];
    float* out = (float*)d_out;

    k1_reduce_topk<<<T_ / TK_, 256>>>(x, w1, b1, g1, bt1);
    k2_expand<<<B_ * POOL_, DIM_>>>(w2, b2, g2, bt2);
    k3_gather<<<(B_ * T_ * K_) / 64, 512>>>(out);
}